// round 17
// baseline (speedup 1.0000x reference)
#include <cuda_runtime.h>
#include <cstdint>

#define T_SEQ 128
#define BATCH 512
#define DIM   128
#define NQ    8
#define NCH   32   // 4 gates * 8 wires

typedef unsigned long long u64;

// Scratch: zpre[(t*BATCH+b)*32 + ch] = x_t[b] @ Wx[:,ch], ch = gate*8+wire
__device__ float g_zpre[(size_t)T_SEQ * BATCH * NCH];
// grid barrier counter (self-resetting each run)
__device__ int g_bar;

__device__ __forceinline__ float tanh_approx(float x) {
    float r;
    asm("tanh.approx.f32 %0, %1;" : "=f"(r) : "f"(x));
    return r;
}
__device__ __forceinline__ void ffma2(u64& acc, u64 a, u64 b) {
    asm("fma.rn.f32x2 %0, %1, %2, %0;" : "+l"(acc) : "l"(a), "l"(b));
}
__device__ __forceinline__ u64 pack2(float lo, float hi) {
    u64 r; asm("mov.b64 %0, {%1, %2};" : "=l"(r) : "f"(lo), "f"(hi)); return r;
}
__device__ __forceinline__ int ld_acquire(const int* p) {
    int v;
    asm volatile("ld.acquire.gpu.s32 %0, [%1];" : "=r"(v) : "l"(p) : "memory");
    return v;
}

// ---------------------------------------------------------------------------
// ONE kernel, 512 blocks x 128 threads.
// Phase 1 (ALL 512 blocks): the proven GEMM tile — identical occupancy and
//   speed to the standalone kernel (~8-10us). Block b covers flattened rows
//   [128b, 128b+128) of (t*BATCH+row); publishes via fence + atomicAdd.
// Barrier: blocks 128-511 exit; blocks 0-127 spin until counter==512.
//   All 512 blocks are co-resident (33KB smem -> 6 blocks/SM -> 888 slots),
//   and producers never wait, so the spin cannot deadlock.
// Phase 2 (blocks 0-127): the proven R16 recurrence (17 independent shfls),
//   byte-identical body.
// Quantum layer (analytic): <Z_w> = prod_{k<=w} cos(phi_k) (w>=1),
//                           <Z_0> = prod_{k=1..7} cos(phi_k).
// ---------------------------------------------------------------------------
__global__ void __launch_bounds__(128) qlstm_all(
    const float* __restrict__ x,
    const float* __restrict__ Wf, const float* __restrict__ bf, const float* __restrict__ thf,
    const float* __restrict__ Wi, const float* __restrict__ bi, const float* __restrict__ thi,
    const float* __restrict__ Wu, const float* __restrict__ bu, const float* __restrict__ thu,
    const float* __restrict__ Wo, const float* __restrict__ bo, const float* __restrict__ tho,
    float* __restrict__ out)
{
    __shared__ __align__(16) float ws[128][32];
    __shared__ float xs[32][129];

    const int tid  = threadIdx.x;
    const int lane = tid & 31;

    // ===================== Phase 1: GEMM (proven body) =====================
    {
        const int row0 = blockIdx.x * 128;

        #pragma unroll 4
        for (int i = tid; i < 128 * 32; i += 128) {
            int k = i >> 5, j = i & 31;
            int g = j >> 3, w = j & 7;
            const float* Wg = (g == 0) ? Wf : (g == 1) ? Wi : (g == 2) ? Wu : Wo;
            ws[k][j] = Wg[k * 8 + w];
        }

        const int c0 = (tid >> 5) * 8;

        u64 acc[4][4];
        #pragma unroll
        for (int r = 0; r < 4; r++)
            #pragma unroll
            for (int q = 0; q < 4; q++) acc[r][q] = 0ull;

        for (int kc = 0; kc < 4; ++kc) {
            __syncthreads();
            #pragma unroll 4
            for (int i = tid; i < 128 * 32; i += 128) {
                int r = i >> 5, kk = i & 31;
                xs[kk][r] = x[(size_t)(row0 + r) * DIM + kc * 32 + kk];
            }
            __syncthreads();

            #pragma unroll
            for (int k = 0; k < 32; ++k) {
                float xv0 = xs[k][lane      ];
                float xv1 = xs[k][lane + 32 ];
                float xv2 = xs[k][lane + 64 ];
                float xv3 = xs[k][lane + 96 ];
                u64 xx0 = pack2(xv0, xv0);
                u64 xx1 = pack2(xv1, xv1);
                u64 xx2 = pack2(xv2, xv2);
                u64 xx3 = pack2(xv3, xv3);
                const u64* wk = reinterpret_cast<const u64*>(&ws[kc * 32 + k][c0]);
                u64 w0 = wk[0], w1 = wk[1], w2 = wk[2], w3 = wk[3];
                ffma2(acc[0][0], xx0, w0); ffma2(acc[0][1], xx0, w1);
                ffma2(acc[0][2], xx0, w2); ffma2(acc[0][3], xx0, w3);
                ffma2(acc[1][0], xx1, w0); ffma2(acc[1][1], xx1, w1);
                ffma2(acc[1][2], xx1, w2); ffma2(acc[1][3], xx1, w3);
                ffma2(acc[2][0], xx2, w0); ffma2(acc[2][1], xx2, w1);
                ffma2(acc[2][2], xx2, w2); ffma2(acc[2][3], xx2, w3);
                ffma2(acc[3][0], xx3, w0); ffma2(acc[3][1], xx3, w1);
                ffma2(acc[3][2], xx3, w2); ffma2(acc[3][3], xx3, w3);
            }
        }

        #pragma unroll
        for (int rr = 0; rr < 4; ++rr) {
            int r = row0 + lane + 32 * rr;
            u64* dst = reinterpret_cast<u64*>(g_zpre + (size_t)r * NCH + c0);
            dst[0] = acc[rr][0]; dst[1] = acc[rr][1];
            dst[2] = acc[rr][2]; dst[3] = acc[rr][3];
        }

        // publish
        __threadfence();
        __syncthreads();
        if (tid == 0) atomicAdd(&g_bar, 1);
    }

    if (blockIdx.x >= 128) return;                 // producers done

    // barrier: wait for all 512 GEMM tiles
    if (tid == 0) {
        while (ld_acquire(&g_bar) < 512) __nanosleep(64);
    }
    __syncthreads();

    // ===================== Phase 2: recurrence (proven R16 body) ============
    const int warp = tid >> 5;
    const int row  = blockIdx.x * 4 + warp;       // 0..511
    const int gate = lane >> 3;
    const int wire = lane & 7;
    const int base = lane & 24;                    // gate*8

    const float* Wg = (gate == 0) ? Wf : (gate == 1) ? Wi : (gate == 2) ? Wu : Wo;
    const float* bg = (gate == 0) ? bf : (gate == 1) ? bi : (gate == 2) ? bu : bo;
    const float* tg = (gate == 0) ? thf : (gate == 1) ? thi : (gate == 2) ? thu : tho;

    // rotated recurrent weights: slot j carries h_{(wire+j)&7}
    float whr[8];
    int hsrc[8];
    int csrc[8];
    #pragma unroll
    for (int j = 0; j < 8; ++j) {
        int kj = (wire + j) & 7;
        whr[j]  = Wg[(DIM + kj) * NQ + wire];
        hsrc[j] = kj;                              // gate-0 lane holding h_kj
        csrc[j] = base + kj;                       // own-segment lane holding c_kj
    }
    const int asrc1 = wire + 8 * ((gate + 1) & 3);
    const int asrc2 = wire + 8 * ((gate + 2) & 3);
    const int asrc3 = wire + 8 * ((gate + 3) & 3);

    const float cbias = bg[wire] + tg[wire];
    const bool  isU   = (gate == 2);
    const float aScl  = isU ? 1.0f : 0.5f;
    const float aMul  = isU ? 1.0f : 0.5f;
    const float aAdd  = isU ? 0.0f : 0.5f;

    const bool w0z = (wire == 0);
    const bool b0 = (wire & 1) != 0;
    const bool b1 = (wire & 2) != 0;
    const bool b2 = (wire & 4) != 0;
    const bool gb0 = (gate & 1) != 0;
    const bool gb1 = (gate & 2) != 0;

    float hv = 0.0f, cstate = 0.0f;

    const float* zp = g_zpre + (size_t)row * NCH + lane;
    const size_t tstride = (size_t)BATCH * NCH;
    float zn0 = zp[0];
    float zn1 = zp[tstride];

    float* outw = out + (size_t)row * NQ + wire;   // step stride = BATCH*NQ

    const unsigned FULL = 0xffffffffu;

    #pragma unroll 2
    for (int t = 0; t < T_SEQ; ++t) {
        float zb = zn0 + cbias;
        zn0 = zn1;
        int t2 = (t + 2 < T_SEQ) ? (t + 2) : (T_SEQ - 1);
        zn1 = zp[(size_t)t2 * tstride];             // off-chain prefetch

        // --- h gather: 7 independent shfls (slot 0 = own hv) ---
        float hs1 = __shfl_sync(FULL, hv, hsrc[1]);
        float hs2 = __shfl_sync(FULL, hv, hsrc[2]);
        float hs3 = __shfl_sync(FULL, hv, hsrc[3]);
        float hs4 = __shfl_sync(FULL, hv, hsrc[4]);
        float hs5 = __shfl_sync(FULL, hv, hsrc[5]);
        float hs6 = __shfl_sync(FULL, hv, hsrc[6]);
        float hs7 = __shfl_sync(FULL, hv, hsrc[7]);

        // z = zb + h . wh (rotated order, two parallel FMA chains)
        float za  = fmaf(hv,  whr[0], zb);
        float zc  = hs1 * whr[1];
        za = fmaf(hs2, whr[2], za);
        zc = fmaf(hs3, whr[3], zc);
        za = fmaf(hs4, whr[4], za);
        zc = fmaf(hs5, whr[5], zc);
        za = fmaf(hs6, whr[6], za);
        zc = fmaf(hs7, whr[7], zc);
        float z = za + zc;

        float c = __cosf(z);

        // --- cos gather: 7 independent shfls (slot 0 = own c) ---
        float a1 = __shfl_sync(FULL, c, csrc[1]);
        float a2 = __shfl_sync(FULL, c, csrc[2]);
        float a3 = __shfl_sync(FULL, c, csrc[3]);
        float a4 = __shfl_sync(FULL, c, csrc[4]);
        float a5 = __shfl_sync(FULL, c, csrc[5]);
        float a6 = __shfl_sync(FULL, c, csrc[6]);
        float a7 = __shfl_sync(FULL, c, csrc[7]);

        // suffix products S_m = prod_{j=m..7} slot_j
        float b67 = a6 * a7;
        float b45 = a4 * a5;
        float b23 = a2 * a3;
        float S7 = a7;
        float S6 = b67;
        float S5 = a5 * b67;
        float S4 = b45 * b67;
        float S3 = a3 * S4;
        float S2 = b23 * S4;
        float S1 = a1 * S2;

        // select S_{8-wire} (wire>=1) / S_1 (wire==0): vals by wire =
        //   {S1, S7, S6, S5, S4, S3, S2, S1}
        float m00 = b0 ? S7 : S1;
        float m01 = b0 ? S5 : S6;
        float m10 = b0 ? S3 : S4;
        float m11 = b0 ? S1 : S2;
        float n0  = b1 ? m01 : m00;
        float n1  = b1 ? m11 : m10;
        float sel = b2 ? n1 : n0;

        float e = w0z ? sel : c * sel;              // <Z_wire>

        // activation: sigmoid via tanh for f,i,o; tanh for u
        float act = fmaf(aMul, tanh_approx(e * aScl), aAdd);

        // --- act gather: 3 independent shfls (slot 0 = own act) ---
        float v1 = __shfl_sync(FULL, act, asrc1);   // gate (g+1)&3
        float v2 = __shfl_sync(FULL, act, asrc2);   // gate (g+2)&3
        float v3 = __shfl_sync(FULL, act, asrc3);   // gate (g+3)&3

        // mux f/i/u/o: slot j holds gate (g+j)&3
        float fv = gb1 ? (gb0 ? v1  : v2) : (gb0 ? v3  : act);
        float iv = gb1 ? (gb0 ? v2  : v3) : (gb0 ? act : v1);
        float uv = gb1 ? (gb0 ? v3  : act) : (gb0 ? v1  : v2);
        float ov = gb1 ? (gb0 ? act : v1) : (gb0 ? v2  : v3);

        cstate = fmaf(fv, cstate, iv * uv);
        hv     = ov * tanh_approx(cstate);

        if (lane < 8)
            outw[(size_t)t * (BATCH * NQ)] = hv;     // predicated store
    }

    if (lane < 8) {
        const size_t outs_sz = (size_t)T_SEQ * BATCH * NQ;
        out[outs_sz + (size_t)row * NQ + wire] = hv;                           // final hx
        out[outs_sz + (size_t)BATCH * NQ + (size_t)row * NQ + wire] = cstate;  // final cx
    }

    // self-reset the barrier for the next graph replay (block 0 finishes
    // long after every consumer has passed the spin)
    __syncthreads();
    if (blockIdx.x == 0 && tid == 0) atomicExch(&g_bar, 0);
}

// ---------------------------------------------------------------------------
// Launch — single kernel, 512 blocks x 128 threads.
// ---------------------------------------------------------------------------
extern "C" void kernel_launch(void* const* d_in, const int* in_sizes, int n_in,
                              void* d_out, int out_size)
{
    const float* x   = (const float*)d_in[0];
    const float* Wf  = (const float*)d_in[1];
    const float* bf  = (const float*)d_in[2];
    const float* thf = (const float*)d_in[3];
    const float* Wi  = (const float*)d_in[4];
    const float* bi  = (const float*)d_in[5];
    const float* thi = (const float*)d_in[6];
    const float* Wu  = (const float*)d_in[7];
    const float* bu  = (const float*)d_in[8];
    const float* thu = (const float*)d_in[9];
    const float* Wo  = (const float*)d_in[10];
    const float* bo  = (const float*)d_in[11];
    const float* tho = (const float*)d_in[12];
    float* out = (float*)d_out;

    qlstm_all<<<512, 128>>>(x,
                            Wf, bf, thf, Wi, bi, thi,
                            Wu, bu, thu, Wo, bo, tho, out);
}